// round 1
// baseline (speedup 1.0000x reference)
#include <cuda_runtime.h>
#include <cuda_bf16.h>

#define NPOP   1024
#define MM     64
#define CC     4
#define NSTEPS 100
#define PAD    68          // 64 + 4 floats row padding: conflict-free LDS.128

// Scratch (static __device__ arrays are the allowed scratch mechanism)
__device__ float g_ntot[NPOP * MM];            // 256 KB
__device__ float g_rti [NPOP * MM * MM];       // 16 MB: Rt[n,i,j] / ntot[n,j]

// ---------------------------------------------------------------------------
// Kernel A: column sums  ntot[n,j] = sum_i R[n,i,j]
// ---------------------------------------------------------------------------
__global__ void ntot_kernel(const float* __restrict__ R) {
    const int n = blockIdx.x;
    const int j = threadIdx.x;
    const float* Rn = R + n * MM * MM;
    float s = 0.f;
#pragma unroll
    for (int i = 0; i < MM; i++) s += Rn[i * MM + j];   // coalesced across j
    g_ntot[n * MM + j] = s;
}

// ---------------------------------------------------------------------------
// Kernel B: rti[f] = Rt.flat[f] / ntot[n,j]
// Rt = transpose(R) (full axis reverse) reshaped (N,M,M): for flat f,
// source = R[(f%1024), (f/1024)%64, f/65536]   (verified mapping)
// ---------------------------------------------------------------------------
__global__ void rti_kernel(const float* __restrict__ R) {
    const int f = blockIdx.x * blockDim.x + threadIdx.x;
    const int src = ((f & 1023) << 12) | (((f >> 10) & 63) << 6) | (f >> 16);
    const float v = __ldg(&R[src]);
    g_rti[f] = v / g_ntot[((f >> 12) << 6) | (f & 63)];
}

// ---------------------------------------------------------------------------
// Main kernel: one CTA per population n, all 100 steps in shared memory.
// 256 threads: thread t -> row i = t>>2, slot q = t&3 (q = compartment in
// the update phase; q = 16-wide j/k chunk in the reduction phases).
// One __syncthreads per step (p and rho double-buffered).
// ---------------------------------------------------------------------------
__global__ __launch_bounds__(256) void step_kernel(
    const float* __restrict__ R,
    const float* __restrict__ Tmat,
    const float* __restrict__ rho0,
    const float* __restrict__ beta,
    float* __restrict__ out)
{
    __shared__ float  sR  [MM * PAD];
    __shared__ float  sRti[MM * PAD];
    __shared__ float  sT  [CC * CC];
    __shared__ float4 sRho[2][MM];     // rho rows as float4, double-buffered
    __shared__ float  sP  [2][MM];     // infection prob p, double-buffered

    const int n = blockIdx.x;
    const int t = threadIdx.x;
    const int i = t >> 2;
    const int q = t & 3;

    // --- one-time loads (coalesced) ---
    const float* Rg = R     + n * MM * MM;
    const float* Gg = g_rti + n * MM * MM;
#pragma unroll
    for (int e = 0; e < 16; e++) {
        const int idx = e * 256 + t;
        const int row = idx >> 6, col = idx & 63;
        sR  [row * PAD + col] = Rg[idx];
        sRti[row * PAD + col] = Gg[idx];
    }
    if (t < 16) sT[t] = Tmat[n * 16 + t];
    float myrho = rho0[n * (MM * CC) + t];          // my (i, c=q) component
    ((float*)&sRho[0][i])[q] = myrho;
    const float bn = __ldg(&beta[n]);
    __syncthreads();

    int cur = 0;
    float* outp = out + n * (MM * CC) + t;
    const float4* rtiRow = (const float4*)(sRti + i * PAD) + q * 4;
    const float4* rRow   = (const float4*)(sR   + i * PAD) + q * 4;

    for (int step = 0; step < NSTEPS; step++) {
        // trajectory records the PRE-update state
        outp[step * (NPOP * MM * CC)] = myrho;

        // ---- phase A: p[i] = 1 - prod_j (1 - a_i * rti[i][j]),  a_i = beta*rho[i][1]
        const float rho1 = __shfl_sync(0xffffffffu, myrho, 1, 4); // quad lane 1 holds c=1
        const float a = bn * rho1;
        float pr0 = 1.f, pr1 = 1.f, pr2 = 1.f, pr3 = 1.f;
#pragma unroll
        for (int e = 0; e < 4; e++) {
            const float4 r4 = rtiRow[e];
            pr0 *= fmaf(-a, r4.x, 1.f);
            pr1 *= fmaf(-a, r4.y, 1.f);
            pr2 *= fmaf(-a, r4.z, 1.f);
            pr3 *= fmaf(-a, r4.w, 1.f);
        }
        float prod = (pr0 * pr1) * (pr2 * pr3);
        prod *= __shfl_xor_sync(0xffffffffu, prod, 1);
        prod *= __shfl_xor_sync(0xffffffffu, prod, 2);
        if (q == 0) sP[cur][i] = 1.f - prod;
        __syncthreads();                              // the ONLY barrier per step

        // ---- phase B: rv[i] = sum_k R[i][k] * p[k]  (butterfly -> all quad lanes)
        float rv = 0.f;
        const float4* pq = (const float4*)(sP[cur]) + q * 4;
#pragma unroll
        for (int e = 0; e < 4; e++) {
            const float4 r4 = rRow[e];
            const float4 p4 = pq[e];
            rv = fmaf(r4.x, p4.x, rv);
            rv = fmaf(r4.y, p4.y, rv);
            rv = fmaf(r4.z, p4.z, rv);
            rv = fmaf(r4.w, p4.w, rv);
        }
        rv += __shfl_xor_sync(0xffffffffu, rv, 1);
        rv += __shfl_xor_sync(0xffffffffu, rv, 2);

        // ---- update: rho_new[i][q] = (rho[i] @ T)[q] + (q==0) * new_inf[i]; clip
        const float4 rr = sRho[cur][i];               // broadcast read of own row
        float acc = rr.x * sT[q];
        acc = fmaf(rr.y, sT[4  + q], acc);
        acc = fmaf(rr.z, sT[8  + q], acc);
        acc = fmaf(rr.w, sT[12 + q], acc);
        if (q == 0) {
            const float tot = (rr.x + rr.y) + (rr.z + rr.w);
            acc = fmaf(1.f - tot, rv, acc);           // new_inf into compartment 0
        }
        acc = fminf(fmaxf(acc, 0.f), 1e10f);
        myrho = acc;
        ((float*)&sRho[cur ^ 1][i])[q] = acc;
        cur ^= 1;
    }
}

// ---------------------------------------------------------------------------
extern "C" void kernel_launch(void* const* d_in, const int* in_sizes, int n_in,
                              void* d_out, int out_size) {
    // Map inputs by element count (robust to ordering): R=4194304, T=16384,
    // rho0=262144, beta=1024.
    const float *R = nullptr, *T = nullptr, *rho0 = nullptr, *beta = nullptr;
    for (int k = 0; k < n_in; k++) {
        switch (in_sizes[k]) {
            case NPOP * MM * MM: R    = (const float*)d_in[k]; break;
            case NPOP * CC * CC: T    = (const float*)d_in[k]; break;
            case NPOP * MM * CC: rho0 = (const float*)d_in[k]; break;
            case NPOP:           beta = (const float*)d_in[k]; break;
        }
    }
    float* out = (float*)d_out;

    ntot_kernel<<<NPOP, MM>>>(R);
    rti_kernel<<<(NPOP * MM * MM) / 256, 256>>>(R);
    step_kernel<<<NPOP, 256>>>(R, T, rho0, beta, out);
}

// round 2
// speedup vs baseline: 2.6458x; 2.6458x over previous
#include <cuda_runtime.h>
#include <cuda_bf16.h>

#define NPOP   1024
#define MM     64
#define CC     4
#define NSTEPS 100
#define CLIPMX 1e10f

// Packed f32x2 helpers (FFMA2/FMUL2 in SASS)
#define FMA2(d,a,b,c) asm("fma.rn.f32x2 %0, %1, %2, %3;" : "=l"(d) : "l"(a), "l"(b), "l"(c))
#define MUL2(d,a,b)   asm("mul.rn.f32x2 %0, %1, %2;"     : "=l"(d) : "l"(a), "l"(b))
#define PACK2(d,lo,hi)   asm("mov.b64 %0, {%1,%2};" : "=l"(d) : "r"(lo), "r"(hi))
#define UNPACK2(lo,hi,d) asm("mov.b64 {%0,%1}, %2;" : "=r"(lo), "=r"(hi) : "l"(d))

typedef unsigned long long u64;

// Scratch
__device__ float g_inv[NPOP * MM];              // 1 / ntot[n][j]
__device__ float g_rt [NPOP * MM * MM];         // Rt (tf-style transpose), un-divided

// ---------------------------------------------------------------------------
// Kernel 1: inv ntot, coalesced.  ntot[n][j] = sum_i R[n][i][j]
// 256 threads: j = t&63, part = t>>6 sums 16 rows (coalesced across t).
// ---------------------------------------------------------------------------
__global__ void ntot_kernel(const float* __restrict__ R) {
    __shared__ float part[256];
    const int n = blockIdx.x, t = threadIdx.x;
    const int j = t & 63, pr = t >> 6;
    const float* Rn = R + n * MM * MM + pr * 16 * MM;
    float s = 0.f;
#pragma unroll
    for (int r = 0; r < 16; r++) s += Rn[r * MM + j];
    part[t] = s;
    __syncthreads();
    if (t < 64)
        g_inv[n * MM + t] = 1.0f / (part[t] + part[t + 64] + part[t + 128] + part[t + 192]);
}

// ---------------------------------------------------------------------------
// Kernel 2: tiled transpose.  Rt.flat[c*65536 + r*1024 + p] = R.flat[p*4096 + r*64 + c]
// (p = source population 0..1023, r = row 0..63, c = col 0..63)
// Both global accesses coalesced via a 32x33 smem tile.
// ---------------------------------------------------------------------------
__global__ void transpose_kernel(const float* __restrict__ R) {
    __shared__ float tile[32][33];
    const int r  = blockIdx.z;
    const int c0 = blockIdx.y * 32;
    const int p0 = blockIdx.x * 32;
    const int tx = threadIdx.x, ty = threadIdx.y;   // 32 x 8
#pragma unroll
    for (int dy = 0; dy < 4; dy++) {
        const int p = p0 + ty + dy * 8;
        tile[ty + dy * 8][tx] = R[p * 4096 + r * 64 + (c0 + tx)];
    }
    __syncthreads();
#pragma unroll
    for (int dy = 0; dy < 4; dy++) {
        const int c = c0 + ty + dy * 8;
        g_rt[c * 65536 + r * 1024 + (p0 + tx)] = tile[tx][ty + dy * 8];
    }
}

// ---------------------------------------------------------------------------
// Kernel 3: 100 timesteps, one CTA per population.
// 256 threads: thread t -> row i = t>>2, quad slot q = t&3.
// Loop-invariant operands (R row chunk, Rt/ntot chunk, T column) in REGISTERS.
// Only p[64] goes through smem (conflict-free padded layout, double-buffered).
// Math in packed f32x2. One barrier per step.
// ---------------------------------------------------------------------------
__global__ __launch_bounds__(256) void step_kernel(
    const float* __restrict__ R,
    const float* __restrict__ Tmat,
    const float* __restrict__ rho0,
    const float* __restrict__ beta,
    float* __restrict__ out)
{
    __shared__ float s_inv[64];
    __shared__ float s_T[16];
    __shared__ __align__(16) float s_p[2][96];   // 4 chunks of 16, stride 24 (conflict-free)

    const int n = blockIdx.x, t = threadIdx.x;
    const int i = t >> 2, q = t & 3;

    if (t < 64) s_inv[t] = g_inv[n * 64 + t];
    if (t < 16) s_T[t]   = Tmat[n * 16 + t];
    __syncthreads();

    // ---- loop-invariant registers ----
    ulonglong2 vR[4], vG[4];                      // 16 floats each, as f32x2 pairs
    {
        const ulonglong2* pR = (const ulonglong2*)(R    + n * 4096 + i * 64 + q * 16);
        const ulonglong2* pG = (const ulonglong2*)(g_rt + n * 4096 + i * 64 + q * 16);
#pragma unroll
        for (int e = 0; e < 4; e++) { vR[e] = pR[e]; vG[e] = pG[e]; }
        // vG *= 1/ntot[j]  (packed)
        const float* ib = s_inv + q * 16;
#pragma unroll
        for (int e = 0; e < 4; e++) {
            const u64 i0 = *(const u64*)(ib + e * 4);
            const u64 i1 = *(const u64*)(ib + e * 4 + 2);
            MUL2(vG[e].x, vG[e].x, i0);
            MUL2(vG[e].y, vG[e].y, i1);
        }
    }
    // per-thread T coefficients: acc(q) = sum_c rho[c] * T[c][q], c ordered {q, q^1, q^2, q^3}
    const float T0 = s_T[(q    ) * 4 + q];
    const float T1 = s_T[(q ^ 1) * 4 + q];
    const float T2 = s_T[(q ^ 2) * 4 + q];
    const float T3 = s_T[(q ^ 3) * 4 + q];

    const float nbn = -__ldg(&beta[n]);
    float myrho = rho0[n * 256 + t];              // my (row i, compartment q)
    const u64 ONE2 = 0x3F8000003F800000ULL;

    float* outp = out + n * 256 + t;

#pragma unroll 2
    for (int step = 0; step < NSTEPS; step++) {
        const int cur = step & 1;
        outp[0] = myrho;                          // trajectory = pre-update state
        outp += NPOP * 256;

        // quad exchange: x1 = rho[q^1], x2 = rho[q^2], x3 = rho[q^3]
        const float x1 = __shfl_xor_sync(0xffffffffu, myrho, 1);
        const float x2 = __shfl_xor_sync(0xffffffffu, myrho, 2);
        const float x3 = __shfl_xor_sync(0xffffffffu, x1,    2);
        const float rho1 = (q == 1) ? myrho : (q == 0) ? x1 : (q == 3) ? x2 : x3;

        // ---- phase A: p[i] = 1 - prod_j (1 - beta*rho1 * Rt[i][j]/ntot[j]) ----
        const float na = nbn * rho1;              // -beta*rho1
        u64 na2; PACK2(na2, __float_as_uint(na), __float_as_uint(na));
        u64 f0, f1, f2, f3, f4, f5, f6, f7;
        FMA2(f0, na2, vG[0].x, ONE2);  FMA2(f1, na2, vG[0].y, ONE2);
        FMA2(f2, na2, vG[1].x, ONE2);  FMA2(f3, na2, vG[1].y, ONE2);
        FMA2(f4, na2, vG[2].x, ONE2);  FMA2(f5, na2, vG[2].y, ONE2);
        FMA2(f6, na2, vG[3].x, ONE2);  FMA2(f7, na2, vG[3].y, ONE2);
        MUL2(f0, f0, f1); MUL2(f2, f2, f3); MUL2(f4, f4, f5); MUL2(f6, f6, f7);
        MUL2(f0, f0, f2); MUL2(f4, f4, f6);
        MUL2(f0, f0, f4);
        unsigned lo, hi; UNPACK2(lo, hi, f0);
        float prod = __uint_as_float(lo) * __uint_as_float(hi);
        prod *= __shfl_xor_sync(0xffffffffu, prod, 1);
        prod *= __shfl_xor_sync(0xffffffffu, prod, 2);
        if (q == 0) s_p[cur][(i >> 4) * 24 + (i & 15)] = 1.0f - prod;
        __syncthreads();                          // the only barrier per step

        // ---- phase B: rv[i] = sum_k R[i][k] * p[k] ----
        const ulonglong2* pp = (const ulonglong2*)(&s_p[cur][q * 24]);
        u64 a0 = 0ull, a1 = 0ull;
#pragma unroll
        for (int e = 0; e < 4; e++) {
            const ulonglong2 p2 = pp[e];
            FMA2(a0, vR[e].x, p2.x, a0);
            FMA2(a1, vR[e].y, p2.y, a1);
        }
        u64 asum; asm("add.rn.f32x2 %0, %1, %2;" : "=l"(asum) : "l"(a0), "l"(a1));
        unsigned rl, rh; UNPACK2(rl, rh, asum);
        float rv = __uint_as_float(rl) + __uint_as_float(rh);
        rv += __shfl_xor_sync(0xffffffffu, rv, 1);
        rv += __shfl_xor_sync(0xffffffffu, rv, 2);

        // ---- update: rho_new = rho @ T  (+ new infections into compartment 0), clip ----
        float acc = myrho * T0;
        acc = fmaf(x1, T1, acc);
        acc = fmaf(x2, T2, acc);
        acc = fmaf(x3, T3, acc);
        if (q == 0) {
            const float tot = (myrho + x1) + (x2 + x3);
            acc = fmaf(1.0f - tot, rv, acc);
        }
        myrho = fminf(fmaxf(acc, 0.0f), CLIPMX);
    }
}

// ---------------------------------------------------------------------------
extern "C" void kernel_launch(void* const* d_in, const int* in_sizes, int n_in,
                              void* d_out, int out_size) {
    const float *R = nullptr, *T = nullptr, *rho0 = nullptr, *beta = nullptr;
    for (int k = 0; k < n_in; k++) {
        switch (in_sizes[k]) {
            case NPOP * MM * MM: R    = (const float*)d_in[k]; break;
            case NPOP * CC * CC: T    = (const float*)d_in[k]; break;
            case NPOP * MM * CC: rho0 = (const float*)d_in[k]; break;
            case NPOP:           beta = (const float*)d_in[k]; break;
        }
    }
    float* out = (float*)d_out;

    ntot_kernel<<<NPOP, 256>>>(R);
    dim3 tgrid(32, 2, 64), tblk(32, 8);
    transpose_kernel<<<tgrid, tblk>>>(R);
    step_kernel<<<NPOP, 256>>>(R, T, rho0, beta, out);
}

// round 3
// speedup vs baseline: 3.6380x; 1.3750x over previous
#include <cuda_runtime.h>
#include <cuda_bf16.h>

#define NPOP   1024
#define MM     64
#define CC     4
#define NSTEPS 100
#define CLIPMX 1e10f

// Packed f32x2 helpers (FFMA2/FMUL2 in SASS, sm_100+)
#define FMA2(d,a,b,c) asm("fma.rn.f32x2 %0, %1, %2, %3;" : "=l"(d) : "l"(a), "l"(b), "l"(c))
#define MUL2(d,a,b)   asm("mul.rn.f32x2 %0, %1, %2;"     : "=l"(d) : "l"(a), "l"(b))
#define ADD2(d,a,b)   asm("add.rn.f32x2 %0, %1, %2;"     : "=l"(d) : "l"(a), "l"(b))
#define PACK2(d,lo,hi)   asm("mov.b64 %0, {%1,%2};" : "=l"(d) : "r"(lo), "r"(hi))
#define UNPACK2(lo,hi,d) asm("mov.b64 {%0,%1}, %2;" : "=r"(lo), "=r"(hi) : "l"(d))

typedef unsigned long long u64;

// Scratch
__device__ float g_inv[NPOP * MM];              // 1 / ntot[n][j]
__device__ float g_rt [NPOP * MM * MM];         // Rt (tf-style full-reverse transpose)

// ---------------------------------------------------------------------------
// Kernel 1: inv column sums.  ntot[n][j] = sum_i R[n][i][j]
// ---------------------------------------------------------------------------
__global__ void ntot_kernel(const float* __restrict__ R) {
    __shared__ float part[256];
    const int n = blockIdx.x, t = threadIdx.x;
    const int j = t & 63, pr = t >> 6;
    const float* Rn = R + n * MM * MM + pr * 16 * MM;
    float s = 0.f;
#pragma unroll
    for (int r = 0; r < 16; r++) s += Rn[r * MM + j];
    part[t] = s;
    __syncthreads();
    if (t < 64)
        g_inv[n * MM + t] = 1.0f / (part[t] + part[t + 64] + part[t + 128] + part[t + 192]);
}

// ---------------------------------------------------------------------------
// Kernel 2: tiled transpose.  Rt.flat[c*65536 + r*1024 + p] = R.flat[p*4096 + r*64 + c]
// ---------------------------------------------------------------------------
__global__ void transpose_kernel(const float* __restrict__ R) {
    __shared__ float tile[32][33];
    const int r  = blockIdx.z;
    const int c0 = blockIdx.y * 32;
    const int p0 = blockIdx.x * 32;
    const int tx = threadIdx.x, ty = threadIdx.y;   // 32 x 8
#pragma unroll
    for (int dy = 0; dy < 4; dy++) {
        const int p = p0 + ty + dy * 8;
        tile[ty + dy * 8][tx] = R[p * 4096 + r * 64 + (c0 + tx)];
    }
    __syncthreads();
#pragma unroll
    for (int dy = 0; dy < 4; dy++) {
        const int c = c0 + ty + dy * 8;
        g_rt[c * 65536 + r * 1024 + (p0 + tx)] = tile[tx][ty + dy * 8];
    }
}

// ---------------------------------------------------------------------------
// Kernel 3: 100 timesteps. 2 populations per 256-thread CTA.
// Within a pop (128 threads): thread u -> row i = u>>1, half h = u&1,
// owning 32 columns [h*32, h*32+32) of BOTH R and Rt/ntot rows (registers),
// and rho compartments (2h, 2h+1) as a packed pair.
// 4 SHFL + 1 BAR + 8 LDS.128 + 1 STG.64 per step; all math in f32x2.
// ---------------------------------------------------------------------------
__global__ __launch_bounds__(256, 2) void step_kernel(
    const float* __restrict__ R,
    const float* __restrict__ Tmat,
    const float* __restrict__ rho0,
    const float* __restrict__ beta,
    float* __restrict__ out)
{
    __shared__ float s_inv[2][64];
    // p buffer: halves at float-offsets 0 and 40 -> even/odd lanes hit
    // disjoint bank groups on every LDS.128 (conflict-free).
    __shared__ __align__(16) float s_p[2][2][80];   // [pop][buf][.]

    const int t  = threadIdx.x;
    const int pl = t >> 7;                 // pop slot in CTA
    const int n  = blockIdx.x * 2 + pl;
    const int u  = t & 127;
    const int i  = u >> 1;                 // row
    const int h  = u & 1;                  // half

    if (u < 64) s_inv[pl][u] = g_inv[n * 64 + u];
    __syncthreads();

    // ---- loop-invariant registers: 32 floats each of Rt/ntot and R ----
    u64 vG[16], vR[16];
    {
        const ulonglong2* gp = (const ulonglong2*)(g_rt + n * 4096 + i * 64 + h * 32);
        const ulonglong2* rp = (const ulonglong2*)(R    + n * 4096 + i * 64 + h * 32);
#pragma unroll
        for (int e = 0; e < 8; e++) {
            ulonglong2 a = gp[e]; vG[2*e] = a.x; vG[2*e+1] = a.y;
            ulonglong2 b = rp[e]; vR[2*e] = b.x; vR[2*e+1] = b.y;
        }
        const float* ib = s_inv[pl] + h * 32;
#pragma unroll
        for (int e = 0; e < 16; e++)
            MUL2(vG[e], vG[e], *(const u64*)(ib + 2 * e));
    }

    // ---- T coefficients for my output compartments (2h, 2h+1) ----
    // new rho[c'] = sum_c rho[c] * T[c][c'];  c order: my(lo,hi), opp(lo,hi)
    const int m0 = 2 * h, m1 = 2 * h + 1, o0 = m0 ^ 2, o1 = m1 ^ 2;
    const float* Tn = Tmat + n * 16;
    const float TA0 = Tn[m0*4+m0], TA1 = Tn[m1*4+m0], TA2 = Tn[o0*4+m0], TA3 = Tn[o1*4+m0];
    const float TB0 = Tn[m0*4+m1], TB1 = Tn[m1*4+m1], TB2 = Tn[o0*4+m1], TB3 = Tn[o1*4+m1];

    const float nbn = -__ldg(&beta[n]);
    float2 myr = *(const float2*)(rho0 + n * 256 + i * 4 + 2 * h);   // (rho[2h], rho[2h+1])

    float* outp = out + n * 256 + i * 4 + 2 * h;
    const u64 ONE2 = 0x3F8000003F800000ULL;
    const int pidx = i + ((i >> 5) << 3);  // where h==0 stores p[i] (split layout)

#pragma unroll 2
    for (int step = 0; step < NSTEPS; step++) {
        const int cur = step & 1;
        *(float2*)outp = myr;                         // trajectory = pre-update state
        outp += NPOP * 256;

        // exchange compartment pair with partner lane (lane^1, same row)
        u64 myp; PACK2(myp, __float_as_uint(myr.x), __float_as_uint(myr.y));
        const u64 oppp = __shfl_xor_sync(0xffffffffu, myp, 1);
        unsigned olo, ohi; UNPACK2(olo, ohi, oppp);
        const float o_lo = __uint_as_float(olo), o_hi = __uint_as_float(ohi);

        // rho[i][1] lives in the (c0,c1) pair's hi word
        const float rho1 = h ? o_hi : myr.y;

        // ---- phase A: p[i] = 1 - prod_j (1 - beta*rho1 * Rt[i][j]/ntot[j]) ----
        const float na = nbn * rho1;                  // -beta*rho1
        u64 na2; PACK2(na2, __float_as_uint(na), __float_as_uint(na));
        u64 f[16];
#pragma unroll
        for (int e = 0; e < 16; e++) FMA2(f[e], na2, vG[e], ONE2);
#pragma unroll
        for (int e = 0; e < 8; e++)  MUL2(f[e], f[e], f[e + 8]);
#pragma unroll
        for (int e = 0; e < 4; e++)  MUL2(f[e], f[e], f[e + 4]);
        MUL2(f[0], f[0], f[2]); MUL2(f[1], f[1], f[3]);
        MUL2(f[0], f[0], f[1]);
        unsigned plo, phi; UNPACK2(plo, phi, f[0]);
        float prod = __uint_as_float(plo) * __uint_as_float(phi);
        prod *= __shfl_xor_sync(0xffffffffu, prod, 1);   // combine halves
        if (h == 0) s_p[pl][cur][pidx] = 1.0f - prod;
        __syncthreads();                              // the only barrier per step

        // ---- phase B: rv[i] = sum_k R[i][k] * p[k] ----
        const ulonglong2* pp = (const ulonglong2*)(&s_p[pl][cur][h * 40]);
        u64 a0 = 0, a1 = 0, a2 = 0, a3 = 0;
#pragma unroll
        for (int e = 0; e < 4; e++) {
            ulonglong2 pv0 = pp[2 * e];
            ulonglong2 pv1 = pp[2 * e + 1];
            FMA2(a0, vR[4*e    ], pv0.x, a0);
            FMA2(a1, vR[4*e + 1], pv0.y, a1);
            FMA2(a2, vR[4*e + 2], pv1.x, a2);
            FMA2(a3, vR[4*e + 3], pv1.y, a3);
        }
        ADD2(a0, a0, a1); ADD2(a2, a2, a3); ADD2(a0, a0, a2);
        unsigned rl, rh; UNPACK2(rl, rh, a0);
        float rv = __uint_as_float(rl) + __uint_as_float(rh);
        rv += __shfl_xor_sync(0xffffffffu, rv, 1);       // combine halves

        // ---- update: rho @ T (+ new infections into compartment 0), clip ----
        float a_lo = myr.x * TA0;
        a_lo = fmaf(myr.y, TA1, a_lo);
        a_lo = fmaf(o_lo,  TA2, a_lo);
        a_lo = fmaf(o_hi,  TA3, a_lo);
        float a_hi = myr.x * TB0;
        a_hi = fmaf(myr.y, TB1, a_hi);
        a_hi = fmaf(o_lo,  TB2, a_hi);
        a_hi = fmaf(o_hi,  TB3, a_hi);
        if (h == 0) {
            const float tot = (myr.x + myr.y) + (o_lo + o_hi);
            a_lo = fmaf(1.0f - tot, rv, a_lo);
        }
        myr.x = fminf(fmaxf(a_lo, 0.0f), CLIPMX);
        myr.y = fminf(fmaxf(a_hi, 0.0f), CLIPMX);
    }
}

// ---------------------------------------------------------------------------
extern "C" void kernel_launch(void* const* d_in, const int* in_sizes, int n_in,
                              void* d_out, int out_size) {
    const float *R = nullptr, *T = nullptr, *rho0 = nullptr, *beta = nullptr;
    for (int k = 0; k < n_in; k++) {
        switch (in_sizes[k]) {
            case NPOP * MM * MM: R    = (const float*)d_in[k]; break;
            case NPOP * CC * CC: T    = (const float*)d_in[k]; break;
            case NPOP * MM * CC: rho0 = (const float*)d_in[k]; break;
            case NPOP:           beta = (const float*)d_in[k]; break;
        }
    }
    float* out = (float*)d_out;

    ntot_kernel<<<NPOP, 256>>>(R);
    dim3 tgrid(32, 2, 64), tblk(32, 8);
    transpose_kernel<<<tgrid, tblk>>>(R);
    step_kernel<<<NPOP / 2, 256>>>(R, T, rho0, beta, out);
}